// round 11
// baseline (speedup 1.0000x reference)
#include <cuda_runtime.h>
#include <cstdint>

#define BB 32
#define AA 8400
#define NCH 84
#define NCC 80
#define KTOP 1500
#define TPAD 1536
#define SORTN 2048
#define MAXDET 300
#define NW 47
#define NWP 48
#define ITX 9                                   // ceil(8400/1024)
#define LCAP 128                                // per-warp class list capacity

// ---------------- device scratch (static, allocation-free) ----------------
__device__ uint64_t g_keys[BB * AA];
__device__ uint64_t g_ckey[2][BB][AA];          // candidate KEY lists

__device__ __forceinline__ uint32_t f2o(float f) {
    uint32_t u = __float_as_uint(f);
    return (u & 0x80000000u) ? ~u : (u | 0x80000000u);
}
__device__ __forceinline__ float o2f(uint32_t u) {
    return (u & 0x80000000u) ? __uint_as_float(u & 0x7FFFFFFFu)
                             : __uint_as_float(~u);
}

// ---------------- stage 1: score max/argmax (4-way class split) ----------------
__global__ void __launch_bounds__(256) k_score(const float* __restrict__ pred) {
    const int Q = AA / 4;
    int t = blockIdx.x * blockDim.x + threadIdx.x;
    int b = blockIdx.y;
    int q = t >> 2;
    int h = t & 3;
    bool active = q < Q;
    if (q >= Q) q = Q - 1;

    const float4* p4 = (const float4*)pred;
    size_t base = ((size_t)b * NCH + 4) * Q + q;
    int c0 = h * 20;

    float4 best = p4[base + (size_t)c0 * Q];
    int cx = c0, cy = c0, cz = c0, cw = c0;
#pragma unroll
    for (int k = 1; k < 20; k++) {
        int c = c0 + k;
        float4 v = p4[base + (size_t)c * Q];
        if (v.x > best.x) { best.x = v.x; cx = c; }
        if (v.y > best.y) { best.y = v.y; cy = c; }
        if (v.z > best.z) { best.z = v.z; cz = c; }
        if (v.w > best.w) { best.w = v.w; cw = c; }
    }

    float sc[4] = {best.x, best.y, best.z, best.w};
    int   cl[4] = {cx, cy, cz, cw};
#pragma unroll
    for (int step = 1; step <= 2; step <<= 1) {
#pragma unroll
        for (int u = 0; u < 4; u++) {
            float so = __shfl_xor_sync(0xFFFFFFFFu, sc[u], step);
            int   co = __shfl_xor_sync(0xFFFFFFFFu, cl[u], step);
            if (so > sc[u] || (so == sc[u] && co < cl[u])) { sc[u] = so; cl[u] = co; }
        }
    }

    if (h == 0 && active) {
        int a0 = q * 4;
#pragma unroll
        for (int u = 0; u < 4; u++) {
            int a = a0 + u;
            float msc = (sc[u] > 0.25f) ? sc[u] : -1.0f;
            uint32_t lo = ((uint32_t)(AA - 1 - a) << 7) | (uint32_t)cl[u];
            g_keys[b * AA + a] = ((uint64_t)f2o(msc) << 32) | lo;
        }
    }
}

// ---------------- stage 2: fused select + sort + NMS + output (1 CTA / image) ----------------
// dynamic smem layout
#define SM_SORT 0                               // u64[2048]        16384
#define SM_BOX  16384                           // float4[1536]     24576
#define SM_LIST 40960                           // u16[32][128]      8192
#define SM_SUPP 49152                           // u32[32][48]       6144
#define SM_HIST 55296                           // u32[256]          1024
#define SM_TOTAL 56320

__global__ void __launch_bounds__(1024) k_main(const float* __restrict__ pred,
                                               float* __restrict__ out) {
    extern __shared__ __align__(16) char sm[];
    uint64_t* sortbuf = (uint64_t*)(sm + SM_SORT);
    float4*   nmsbox  = (float4*)(sm + SM_BOX);
    uint16_t* slistA  = (uint16_t*)(sm + SM_LIST);
    uint32_t* suppA   = (uint32_t*)(sm + SM_SUPP);
    uint32_t* hist    = (uint32_t*)(sm + SM_HIST);
    __shared__ uint32_t s_selCnt, s_candCnt;
    __shared__ int s_dstar, s_above;
    __shared__ uint32_t sKeep[NWP], wpre[NWP];

    int b = blockIdx.x, tid = threadIdx.x;
    int warp = tid >> 5, lane = tid & 31;
    uint32_t lmlt = (1u << lane) - 1u;
    const float* pb = pred + (size_t)b * NCH * AA;
    float* ob = out + (size_t)b * (MAXDET * 6);

    for (int i = tid; i < SORTN; i += 1024) sortbuf[i] = 0;
    for (int i = tid; i < MAXDET * 6; i += 1024) ob[i] = 0.0f;
    if (tid < NWP) sKeep[tid] = 0;
    if (tid == 0) s_selCnt = 0;
    __syncthreads();

    // ---- radix select with batched loads (R10) ----
    const uint64_t* L = g_keys + (size_t)b * AA;
    int ncand = AA, kRem = KTOP, cur = 0;

    for (int pass = 0; pass < 8; pass++) {
        int shift = 56 - 8 * pass;
        if (tid < 256) hist[tid] = 0;
        __syncthreads();

        uint64_t kv[ITX];
#pragma unroll
        for (int it = 0; it < ITX; it++) {
            int i = tid + (it << 10);
            kv[it] = (i < ncand) ? L[i] : 0ull;
        }
#pragma unroll
        for (int it = 0; it < ITX; it++) {
            int i = tid + (it << 10);
            if (i < ncand)
                atomicAdd(&hist[(uint32_t)(kv[it] >> shift) & 0xFFu], 1u);
        }
        __syncthreads();

        if (tid < 32) {
            int base = 255 - lane * 8;
            uint32_t h[8]; uint32_t sum = 0;
#pragma unroll
            for (int k = 0; k < 8; k++) { h[k] = hist[base - k]; sum += h[k]; }
            uint32_t pre = sum;
#pragma unroll
            for (int off = 1; off < 32; off <<= 1) {
                uint32_t v = __shfl_up_sync(0xFFFFFFFFu, pre, off);
                if (lane >= off) pre += v;
            }
            uint32_t cum = pre - sum;
#pragma unroll
            for (int k = 0; k < 8; k++) {
                int d = base - k;
                if (cum < (uint32_t)kRem && cum + h[k] >= (uint32_t)kRem) {
                    s_dstar = d; s_above = (int)cum;
                }
                cum += h[k];
            }
        }
        if (tid == 0) s_candCnt = 0;
        __syncthreads();

        uint32_t ds = (uint32_t)s_dstar;
        int above = s_above;
        int bc = (int)hist[ds];
        int scnt = (int)s_selCnt;
        bool last = (scnt + above + bc <= SORTN) || (pass == 7);

        uint64_t* Lnext = g_ckey[cur][b];
#pragma unroll
        for (int it = 0; it < ITX; it++) {
            int i = tid + (it << 10);
            bool valid = i < ncand;
            uint32_t d = valid ? ((uint32_t)(kv[it] >> shift) & 0xFFu) : 0u;
            bool toSel  = valid && (d > ds || (last && d == ds));
            bool toCand = valid && !last && (d == ds);
            uint32_t balS = __ballot_sync(0xFFFFFFFFu, toSel);
            uint32_t base = 0;
            if (balS) {
                uint32_t ldr = __ffs(balS) - 1;
                if (toSel && lane == (int)ldr)
                    base = atomicAdd(&s_selCnt, (uint32_t)__popc(balS));
                base = __shfl_sync(0xFFFFFFFFu, base, ldr);
                if (toSel) sortbuf[base + __popc(balS & lmlt)] = kv[it];
            }
            uint32_t balC = __ballot_sync(0xFFFFFFFFu, toCand);
            uint32_t baseC = 0;
            if (balC) {
                uint32_t ldr = __ffs(balC) - 1;
                if (toCand && lane == (int)ldr)
                    baseC = atomicAdd(&s_candCnt, (uint32_t)__popc(balC));
                baseC = __shfl_sync(0xFFFFFFFFu, baseC, ldr);
                if (toCand) Lnext[baseC + __popc(balC & lmlt)] = kv[it];
            }
        }
        __syncthreads();
        if (last) break;
        kRem -= above;
        ncand = (int)s_candCnt;
        L = Lnext;
        cur ^= 1;
        __syncthreads();
    }

    // ---- pair-indexed bitonic sort descending, n=2048 ----
    for (int kk = 2; kk <= SORTN; kk <<= 1) {
        for (int j = kk >> 1; j > 0; j >>= 1) {
            int p0 = ((tid & ~(j - 1)) << 1) | (tid & (j - 1));
            int p1 = p0 | j;
            uint64_t x = sortbuf[p0], y = sortbuf[p1];
            bool desc = (p0 & kk) == 0;
            if (desc ? (x < y) : (x > y)) { sortbuf[p0] = y; sortbuf[p1] = x; }
            __syncthreads();
        }
    }

    // ---- build nmsbox in smem (gather boxes for top-1500) ----
    const float SC1 = (float)(1.0 / 80.0 / 640.0);
    const float MULT = (float)(1.0 / 80.0);
    const uint32_t F025 = f2o(0.25f);
    for (int r = tid; r < KTOP; r += 1024) {
        uint64_t k = sortbuf[r];
        uint32_t lo = (uint32_t)k;
        int cls = (int)(lo & 0x7Fu);
        uint32_t a = (uint32_t)(AA - 1) - (lo >> 7);
        float bx0 = pb[(size_t)0 * AA + a];
        float bx1 = pb[(size_t)1 * AA + a];
        float bx2 = pb[(size_t)2 * AA + a];
        float bx3 = pb[(size_t)3 * AA + a];
        float off = (float)cls * MULT;
        nmsbox[r] = make_float4(bx0 * SC1 + off, bx1 * SC1 + off,
                                bx2 * SC1 + off, bx3 * SC1 + off);
    }
    __syncthreads();

    // ---- per-class warp NMS: classes striped over 32 warps ----
    uint16_t* slist = slistA + warp * LCAP;
    uint32_t* sp = suppA + warp * NWP;
    for (int c = warp; c < NCC; c += 32) {
        // build rank-ordered list of class-c candidates from sortbuf keys
        int cnt = 0;
        for (int w = 0; w < NW; w++) {
            int r = w * 32 + lane;
            bool m = false;
            if (r < KTOP) {
                uint64_t k = sortbuf[r];
                m = ((uint32_t)(k >> 32) > F025) && (((uint32_t)k & 0x7Fu) == (uint32_t)c);
            }
            uint32_t bal = __ballot_sync(0xFFFFFFFFu, m);
            if (m) {
                int pos = cnt + __popc(bal & lmlt);
                if (pos < LCAP) slist[pos] = (uint16_t)r;
            }
            cnt += __popc(bal);
        }
        int n = cnt;
        if (n == 0) continue;

        if (n <= 32) {
            // register-resident greedy NMS
            float4 mb = make_float4(0.f, 0.f, 0.f, 0.f);
            int myr = -1;
            if (lane < n) { myr = slist[lane]; mb = nmsbox[myr]; }
            float areaM = (mb.z - mb.x) * (mb.w - mb.y);
            uint32_t supp = 0;
            for (int i = 0; i < n; i++) {
                if ((supp >> i) & 1u) continue;
                float ax = __shfl_sync(0xFFFFFFFFu, mb.x, i);
                float ay = __shfl_sync(0xFFFFFFFFu, mb.y, i);
                float az = __shfl_sync(0xFFFFFFFFu, mb.z, i);
                float aw = __shfl_sync(0xFFFFFFFFu, mb.w, i);
                float areaA = (az - ax) * (aw - ay);
                float lx = fmaxf(ax, mb.x), ly = fmaxf(ay, mb.y);
                float rx = fminf(az, mb.z), ry = fminf(aw, mb.w);
                float inter = fmaxf(rx - lx, 0.f) * fmaxf(ry - ly, 0.f);
                float iou = inter / (areaA + areaM - inter + 1e-7f);
                bool sbit = (lane > i) && (lane < n) && (iou > 0.45f);
                supp |= __ballot_sync(0xFFFFFFFFu, sbit);
            }
            if (lane < n && !((supp >> lane) & 1u))
                atomicOr(&sKeep[myr >> 5], 1u << (myr & 31));
        } else if (n <= LCAP) {
            int words = (n + 31) >> 5;
            for (int w = lane; w < words; w += 32) sp[w] = 0;
            __syncwarp();
            for (int i = 0; i < n; i++) {
                if ((sp[i >> 5] >> (i & 31)) & 1u) continue;
                float4 a = nmsbox[slist[i]];
                float areaA = (a.z - a.x) * (a.w - a.y);
                for (int w = i >> 5; w < words; w++) {
                    int j = w * 32 + lane;
                    bool sbit = false;
                    if (j > i && j < n) {
                        float4 bb = nmsbox[slist[j]];
                        float areaB = (bb.z - bb.x) * (bb.w - bb.y);
                        float lx = fmaxf(a.x, bb.x), ly = fmaxf(a.y, bb.y);
                        float rx = fminf(a.z, bb.z), ry = fminf(a.w, bb.w);
                        float inter = fmaxf(rx - lx, 0.f) * fmaxf(ry - ly, 0.f);
                        float iou = inter / (areaA + areaB - inter + 1e-7f);
                        sbit = iou > 0.45f;
                    }
                    uint32_t bal = __ballot_sync(0xFFFFFFFFu, sbit);
                    if (lane == 0 && bal) sp[w] |= bal;
                    __syncwarp();
                }
            }
            for (int j = lane; j < n; j += 32)
                if (!((sp[j >> 5] >> (j & 31)) & 1u)) {
                    int r = slist[j];
                    atomicOr(&sKeep[r >> 5], 1u << (r & 31));
                }
        } else {
            // overflow fallback: rank-bitmap greedy over all 1500 (always correct)
            for (int w = lane; w < NWP; w += 32) sp[w] = 0;
            __syncwarp();
            for (int i = 0; i < KTOP; i++) {
                uint64_t ki = sortbuf[i];
                bool mem = ((uint32_t)(ki >> 32) > F025)
                           && (((uint32_t)ki & 0x7Fu) == (uint32_t)c)
                           && !((sp[i >> 5] >> (i & 31)) & 1u);
                if (!mem) continue;
                float4 a = nmsbox[i];
                float areaA = (a.z - a.x) * (a.w - a.y);
                for (int w = i >> 5; w < NW; w++) {
                    int j = w * 32 + lane;
                    bool sbit = false;
                    if (j > i && j < KTOP) {
                        uint64_t kj = sortbuf[j];
                        if (((uint32_t)(kj >> 32) > F025)
                            && (((uint32_t)kj & 0x7Fu) == (uint32_t)c)) {
                            float4 bb = nmsbox[j];
                            float areaB = (bb.z - bb.x) * (bb.w - bb.y);
                            float lx = fmaxf(a.x, bb.x), ly = fmaxf(a.y, bb.y);
                            float rx = fminf(a.z, bb.z), ry = fminf(a.w, bb.w);
                            float inter = fmaxf(rx - lx, 0.f) * fmaxf(ry - ly, 0.f);
                            float iou = inter / (areaA + areaB - inter + 1e-7f);
                            sbit = iou > 0.45f;
                        }
                    }
                    uint32_t bal = __ballot_sync(0xFFFFFFFFu, sbit);
                    if (lane == 0 && bal) sp[w] |= bal;
                    __syncwarp();
                }
            }
            for (int r = lane; r < KTOP; r += 32) {
                uint64_t kr = sortbuf[r];
                bool mem = ((uint32_t)(kr >> 32) > F025)
                           && (((uint32_t)kr & 0x7Fu) == (uint32_t)c)
                           && !((sp[r >> 5] >> (r & 31)) & 1u);
                if (mem) atomicOr(&sKeep[r >> 5], 1u << (r & 31));
            }
        }
    }
    __syncthreads();

    // ---- prefix over keep words ----
    if (warp == 0) {
        uint32_t c0 = (lane < NWP) ? __popc(sKeep[lane]) : 0;
        uint32_t inc = c0;
#pragma unroll
        for (int off = 1; off < 32; off <<= 1) {
            uint32_t v = __shfl_up_sync(0xFFFFFFFFu, inc, off);
            if (lane >= off) inc += v;
        }
        if (lane < NWP) wpre[lane] = inc - c0;
        uint32_t tot0 = __shfl_sync(0xFFFFFFFFu, inc, 31);
        uint32_t c1 = (lane + 32 < NWP) ? __popc(sKeep[lane + 32]) : 0;
        uint32_t inc1 = c1;
#pragma unroll
        for (int off = 1; off < 32; off <<= 1) {
            uint32_t v = __shfl_up_sync(0xFFFFFFFFu, inc1, off);
            if (lane >= off) inc1 += v;
        }
        if (lane + 32 < NWP) wpre[lane + 32] = tot0 + inc1 - c1;
    }
    __syncthreads();

    // ---- scatter kept dets in rank order ----
    for (int r = tid; r < KTOP; r += 1024) {
        int w = r >> 5;
        uint32_t word = sKeep[w];
        uint32_t bit = 1u << (r & 31);
        if (word & bit) {
            uint32_t rank = wpre[w] + __popc(word & (bit - 1u));
            if (rank < MAXDET) {
                uint64_t k = sortbuf[r];
                uint32_t hi = (uint32_t)(k >> 32);
                uint32_t lo = (uint32_t)k;
                int cls = (int)(lo & 0x7Fu);
                uint32_t a = (uint32_t)(AA - 1) - (lo >> 7);
                float* o = ob + rank * 6;
                o[0] = pb[(size_t)0 * AA + a];
                o[1] = pb[(size_t)1 * AA + a];
                o[2] = pb[(size_t)2 * AA + a];
                o[3] = pb[(size_t)3 * AA + a];
                o[4] = o2f(hi);
                o[5] = (float)cls;
            }
        }
    }
}

// ---------------- launch ----------------
extern "C" void kernel_launch(void* const* d_in, const int* in_sizes, int n_in,
                              void* d_out, int out_size) {
    const float* pred = (const float*)d_in[0];
    float* out = (float*)d_out;
    cudaFuncSetAttribute(k_main, cudaFuncAttributeMaxDynamicSharedMemorySize,
                         SM_TOTAL);
    k_score<<<dim3((AA + 255) / 256, BB), 256>>>(pred);
    k_main<<<BB, 1024, SM_TOTAL>>>(pred, out);
}

// round 12
// speedup vs baseline: 1.2141x; 1.2141x over previous
#include <cuda_runtime.h>
#include <cstdint>

#define BB 32
#define AA 8400
#define NCH 84
#define NCC 80
#define KTOP 1500
#define TPAD 1536
#define SORTN 2048
#define MAXDET 300
#define NW 47
#define NWP 48
#define ITX 9                                   // ceil(8400/1024)

// ---------------- device scratch (static, allocation-free) ----------------
__device__ uint64_t g_keys[BB * AA];
__device__ uint64_t g_ckey[2][BB][AA];          // candidate KEY lists
__device__ float4   g_selbox[BB * TPAD];
__device__ float4   g_nmsbox[BB * TPAD];
__device__ float    g_selscore[BB * TPAD];
__device__ float    g_selcls[BB * TPAD];
__device__ uint8_t  g_clsSel[BB * TPAD];
__device__ uint32_t g_validbits[BB * NWP];
__device__ uint8_t  g_keepB[BB * TPAD];
__device__ uint32_t g_done[BB];

__device__ __forceinline__ uint32_t f2o(float f) {
    uint32_t u = __float_as_uint(f);
    return (u & 0x80000000u) ? ~u : (u | 0x80000000u);
}
__device__ __forceinline__ float o2f(uint32_t u) {
    return (u & 0x80000000u) ? __uint_as_float(u & 0x7FFFFFFFu)
                             : __uint_as_float(~u);
}
__device__ __forceinline__ uint64_t bshfl(uint64_t v, int i, int kk, int j) {
    uint64_t p = __shfl_xor_sync(0xFFFFFFFFu, v, j);
    bool up = (i & j) == 0;
    bool desc = (i & kk) == 0;
    bool takemax = (up == desc);
    return ((v > p) == takemax) ? v : p;
}

// ---------------- stage 1: score max/argmax (4-way class split) ----------------
__global__ void __launch_bounds__(256) k_score(const float* __restrict__ pred) {
    const int Q = AA / 4;
    int t = blockIdx.x * blockDim.x + threadIdx.x;
    int b = blockIdx.y;
    int q = t >> 2;
    int h = t & 3;
    bool active = q < Q;
    if (q >= Q) q = Q - 1;

    const float4* p4 = (const float4*)pred;
    size_t base = ((size_t)b * NCH + 4) * Q + q;
    int c0 = h * 20;

    float4 best = p4[base + (size_t)c0 * Q];
    int cx = c0, cy = c0, cz = c0, cw = c0;
#pragma unroll
    for (int k = 1; k < 20; k++) {
        int c = c0 + k;
        float4 v = p4[base + (size_t)c * Q];
        if (v.x > best.x) { best.x = v.x; cx = c; }
        if (v.y > best.y) { best.y = v.y; cy = c; }
        if (v.z > best.z) { best.z = v.z; cz = c; }
        if (v.w > best.w) { best.w = v.w; cw = c; }
    }

    float sc[4] = {best.x, best.y, best.z, best.w};
    int   cl[4] = {cx, cy, cz, cw};
#pragma unroll
    for (int step = 1; step <= 2; step <<= 1) {
#pragma unroll
        for (int u = 0; u < 4; u++) {
            float so = __shfl_xor_sync(0xFFFFFFFFu, sc[u], step);
            int   co = __shfl_xor_sync(0xFFFFFFFFu, cl[u], step);
            if (so > sc[u] || (so == sc[u] && co < cl[u])) { sc[u] = so; cl[u] = co; }
        }
    }

    if (h == 0 && active) {
        int a0 = q * 4;
#pragma unroll
        for (int u = 0; u < 4; u++) {
            int a = a0 + u;
            float msc = (sc[u] > 0.25f) ? sc[u] : -1.0f;
            uint32_t lo = ((uint32_t)(AA - 1 - a) << 7) | (uint32_t)cl[u];
            g_keys[b * AA + a] = ((uint64_t)f2o(msc) << 32) | lo;
        }
    }
}

// ---------------- stage 2: batched radix select + hybrid bitonic ----------------
__global__ void __launch_bounds__(1024) k_topk(const float* __restrict__ pred) {
    __shared__ uint32_t hist[256];
    __shared__ uint64_t sortbuf[SORTN];
    __shared__ uint32_t s_selCnt, s_candCnt;
    __shared__ int s_dstar, s_above;

    int b = blockIdx.x, tid = threadIdx.x;
    int lane = tid & 31;
    uint32_t lmlt = (1u << lane) - 1u;

    for (int i = tid; i < SORTN; i += 1024) sortbuf[i] = 0;
    for (int i = tid; i < TPAD; i += 1024) g_keepB[b * TPAD + i] = 0;
    if (tid == 0) { s_selCnt = 0; g_done[b] = 0; }
    __syncthreads();

    const uint64_t* L = g_keys + (size_t)b * AA;
    int ncand = AA, kRem = KTOP, cur = 0;

    for (int pass = 0; pass < 8; pass++) {
        int shift = 56 - 8 * pass;
        if (tid < 256) hist[tid] = 0;
        __syncthreads();

        // batched load: all candidate keys for this thread up front (MLP=9)
        uint64_t kv[ITX];
#pragma unroll
        for (int it = 0; it < ITX; it++) {
            int i = tid + (it << 10);
            kv[it] = (i < ncand) ? L[i] : 0ull;
        }
#pragma unroll
        for (int it = 0; it < ITX; it++) {
            int i = tid + (it << 10);
            if (i < ncand)
                atomicAdd(&hist[(uint32_t)(kv[it] >> shift) & 0xFFu], 1u);
        }
        __syncthreads();

        if (tid < 32) {
            int base = 255 - lane * 8;
            uint32_t h[8]; uint32_t sum = 0;
#pragma unroll
            for (int k = 0; k < 8; k++) { h[k] = hist[base - k]; sum += h[k]; }
            uint32_t pre = sum;
#pragma unroll
            for (int off = 1; off < 32; off <<= 1) {
                uint32_t v = __shfl_up_sync(0xFFFFFFFFu, pre, off);
                if (lane >= off) pre += v;
            }
            uint32_t cum = pre - sum;
#pragma unroll
            for (int k = 0; k < 8; k++) {
                int d = base - k;
                if (cum < (uint32_t)kRem && cum + h[k] >= (uint32_t)kRem) {
                    s_dstar = d; s_above = (int)cum;
                }
                cum += h[k];
            }
        }
        if (tid == 0) s_candCnt = 0;
        __syncthreads();

        uint32_t ds = (uint32_t)s_dstar;
        int above = s_above;
        int bc = (int)hist[ds];
        int scnt = (int)s_selCnt;
        bool last = (scnt + above + bc <= SORTN) || (pass == 7);

        // route sweep reuses kv[] — zero extra loads.
        uint64_t* Lnext = g_ckey[cur][b];
#pragma unroll
        for (int it = 0; it < ITX; it++) {
            int i = tid + (it << 10);
            bool valid = i < ncand;
            uint32_t d = valid ? ((uint32_t)(kv[it] >> shift) & 0xFFu) : 0u;
            bool toSel  = valid && (d > ds || (last && d == ds));
            bool toCand = valid && !last && (d == ds);
            uint32_t balS = __ballot_sync(0xFFFFFFFFu, toSel);
            uint32_t base = 0;
            if (balS) {
                uint32_t ldr = __ffs(balS) - 1;
                if (toSel && lane == (int)ldr)
                    base = atomicAdd(&s_selCnt, (uint32_t)__popc(balS));
                base = __shfl_sync(0xFFFFFFFFu, base, ldr);
                if (toSel) sortbuf[base + __popc(balS & lmlt)] = kv[it];
            }
            uint32_t balC = __ballot_sync(0xFFFFFFFFu, toCand);
            uint32_t baseC = 0;
            if (balC) {
                uint32_t ldr = __ffs(balC) - 1;
                if (toCand && lane == (int)ldr)
                    baseC = atomicAdd(&s_candCnt, (uint32_t)__popc(balC));
                baseC = __shfl_sync(0xFFFFFFFFu, baseC, ldr);
                if (toCand) Lnext[baseC + __popc(balC & lmlt)] = kv[it];
            }
        }
        __syncthreads();
        if (last) break;
        kRem -= above;
        ncand = (int)s_candCnt;
        L = Lnext;
        cur ^= 1;
        __syncthreads();
    }

    // ---- hybrid bitonic sort descending, n=2048 (shfl j<32, smem j>=32) ----
    {
        int i0 = tid, i1 = tid + 1024;
        uint64_t v0 = sortbuf[i0], v1 = sortbuf[i1];
#pragma unroll
        for (int kk = 2; kk <= 32; kk <<= 1)
#pragma unroll
            for (int j = kk >> 1; j >= 1; j >>= 1) {
                v0 = bshfl(v0, i0, kk, j);
                v1 = bshfl(v1, i1, kk, j);
            }
        sortbuf[i0] = v0; sortbuf[i1] = v1;
        __syncthreads();
        for (int kk = 64; kk <= SORTN; kk <<= 1) {
            for (int j = kk >> 1; j >= 32; j >>= 1) {
                int p0 = ((tid & ~(j - 1)) << 1) | (tid & (j - 1));
                int p1 = p0 | j;
                uint64_t x = sortbuf[p0], y = sortbuf[p1];
                bool desc = (p0 & kk) == 0;
                if (desc ? (x < y) : (x > y)) { sortbuf[p0] = y; sortbuf[p1] = x; }
                __syncthreads();
            }
            v0 = sortbuf[i0]; v1 = sortbuf[i1];
#pragma unroll
            for (int j = 16; j >= 1; j >>= 1) {
                v0 = bshfl(v0, i0, kk, j);
                v1 = bshfl(v1, i1, kk, j);
            }
            sortbuf[i0] = v0; sortbuf[i1] = v1;
            __syncthreads();
        }
    }

    // ---- emit per-rank data + validity bitmap ----
    const float* pb = pred + (size_t)b * NCH * AA;
    const float SC1 = (float)(1.0 / 80.0 / 640.0);
    const float MULT = (float)(1.0 / 80.0);
#pragma unroll
    for (int rr = 0; rr < 2; rr++) {
        int r = tid + rr * 1024;
        bool inr = r < TPAD;
        bool validf = false;
        if (r < KTOP) {
            uint64_t k = sortbuf[r];
            uint32_t hi = (uint32_t)(k >> 32);
            uint32_t lo = (uint32_t)k;
            int cls = (int)(lo & 0x7Fu);
            uint32_t a = (uint32_t)(AA - 1) - (lo >> 7);
            float msc = o2f(hi);
            validf = msc > 0.25f;
            float bx0 = pb[(size_t)0 * AA + a];
            float bx1 = pb[(size_t)1 * AA + a];
            float bx2 = pb[(size_t)2 * AA + a];
            float bx3 = pb[(size_t)3 * AA + a];
            int o = b * TPAD + r;
            g_selbox[o] = make_float4(bx0, bx1, bx2, bx3);
            float off = (float)cls * MULT;
            g_nmsbox[o] = make_float4(bx0 * SC1 + off, bx1 * SC1 + off,
                                      bx2 * SC1 + off, bx3 * SC1 + off);
            g_selscore[o] = msc;
            g_selcls[o] = (float)cls;
            g_clsSel[o] = (uint8_t)cls;
        } else if (inr) {
            g_clsSel[b * TPAD + r] = 0xFFu;
        }
        uint32_t vb = __ballot_sync(0xFFFFFFFFu, validf);
        if (lane == 0 && inr) g_validbits[b * NWP + (r >> 5)] = vb;
    }
}

// ---------------- stage 3: per-(image,class) warp NMS + last-block output ----------------
__global__ void k_nms(float* __restrict__ out) {
    __shared__ uint8_t  sCls[TPAD];
    __shared__ uint32_t sValid[NWP];
    __shared__ uint16_t slist[8][TPAD];
    __shared__ uint32_t ssupp[8][NWP];
    __shared__ uint32_t keepw[NWP], wpre[NWP];
    __shared__ int s_last;
    int b = blockIdx.y;
    int tid = threadIdx.x, warp = tid >> 5, lane = tid & 31;
    int c = blockIdx.x * 8 + warp;              // 10 x 8 = 80 classes

    const uint32_t* gc4 = (const uint32_t*)(g_clsSel + b * TPAD);
    uint32_t* sc4 = (uint32_t*)sCls;
    for (int i = tid; i < TPAD / 4; i += 256) sc4[i] = gc4[i];
    if (tid < NWP) sValid[tid] = g_validbits[b * NWP + tid];
    __syncthreads();

    int cnt = 0;
    for (int w = 0; w < NW; w++) {
        int r = w * 32 + lane;
        bool m = (r < KTOP) && ((sValid[w] >> lane) & 1u) && (sCls[r] == (uint8_t)c);
        uint32_t bal = __ballot_sync(0xFFFFFFFFu, m);
        if (m) slist[warp][cnt + __popc(bal & ((1u << lane) - 1u))] = (uint16_t)r;
        cnt += __popc(bal);
    }
    int n = cnt;

    if (n > 0 && n <= 32) {
        float4 mb = make_float4(0.f, 0.f, 0.f, 0.f);
        int myr = -1;
        if (lane < n) { myr = slist[warp][lane]; mb = g_nmsbox[b * TPAD + myr]; }
        float areaM = (mb.z - mb.x) * (mb.w - mb.y);
        uint32_t supp = 0;
        for (int i = 0; i < n; i++) {
            if ((supp >> i) & 1u) continue;
            float ax = __shfl_sync(0xFFFFFFFFu, mb.x, i);
            float ay = __shfl_sync(0xFFFFFFFFu, mb.y, i);
            float az = __shfl_sync(0xFFFFFFFFu, mb.z, i);
            float aw = __shfl_sync(0xFFFFFFFFu, mb.w, i);
            float areaA = (az - ax) * (aw - ay);
            float lx = fmaxf(ax, mb.x), ly = fmaxf(ay, mb.y);
            float rx = fminf(az, mb.z), ry = fminf(aw, mb.w);
            float inter = fmaxf(rx - lx, 0.f) * fmaxf(ry - ly, 0.f);
            float iou = inter / (areaA + areaM - inter + 1e-7f);
            bool sbit = (lane > i) && (lane < n) && (iou > 0.45f);
            supp |= __ballot_sync(0xFFFFFFFFu, sbit);
        }
        if (lane < n && !((supp >> lane) & 1u)) g_keepB[b * TPAD + myr] = 1;
    } else if (n > 32) {
        int words = (n + 31) >> 5;
        for (int w = lane; w < words; w += 32) ssupp[warp][w] = 0;
        __syncwarp();
        for (int i = 0; i < n; i++) {
            if ((ssupp[warp][i >> 5] >> (i & 31)) & 1u) continue;
            float4 a = g_nmsbox[b * TPAD + slist[warp][i]];
            float areaA = (a.z - a.x) * (a.w - a.y);
            for (int w = i >> 5; w < words; w++) {
                int j = w * 32 + lane;
                bool sbit = false;
                if (j > i && j < n) {
                    float4 bb = g_nmsbox[b * TPAD + slist[warp][j]];
                    float areaB = (bb.z - bb.x) * (bb.w - bb.y);
                    float lx = fmaxf(a.x, bb.x), ly = fmaxf(a.y, bb.y);
                    float rx = fminf(a.z, bb.z), ry = fminf(a.w, bb.w);
                    float inter = fmaxf(rx - lx, 0.f) * fmaxf(ry - ly, 0.f);
                    float iou = inter / (areaA + areaB - inter + 1e-7f);
                    sbit = iou > 0.45f;
                }
                uint32_t bal = __ballot_sync(0xFFFFFFFFu, sbit);
                if (lane == 0 && bal) ssupp[warp][w] |= bal;
                __syncwarp();
            }
        }
        for (int j = lane; j < n; j += 32)
            if (!((ssupp[warp][j >> 5] >> (j & 31)) & 1u))
                g_keepB[b * TPAD + slist[warp][j]] = 1;
    }

    // ---- last block of this image performs compaction + output ----
    __threadfence();
    __syncthreads();
    if (tid == 0) s_last = (atomicAdd(&g_done[b], 1u) == gridDim.x - 1);
    __syncthreads();
    if (!s_last) return;

    float* ob = out + (size_t)b * (MAXDET * 6);
    for (int i = tid; i < MAXDET * 6; i += 256) ob[i] = 0.0f;

    uint8_t kb[6];
#pragma unroll
    for (int s = 0; s < 6; s++)
        kb[s] = g_keepB[b * TPAD + (warp * 6 + s) * 32 + lane];
#pragma unroll
    for (int s = 0; s < 6; s++) {
        uint32_t word = __ballot_sync(0xFFFFFFFFu, kb[s] != 0);
        if (lane == 0) keepw[warp * 6 + s] = word;
    }
    __syncthreads();
    if (warp == 0) {
        uint32_t c0 = (lane < NWP) ? __popc(keepw[lane]) : 0;
        uint32_t inc = c0;
#pragma unroll
        for (int off = 1; off < 32; off <<= 1) {
            uint32_t v = __shfl_up_sync(0xFFFFFFFFu, inc, off);
            if (lane >= off) inc += v;
        }
        if (lane < NWP) wpre[lane] = inc - c0;
        uint32_t tot0 = __shfl_sync(0xFFFFFFFFu, inc, 31);
        uint32_t c1 = (lane + 32 < NWP) ? __popc(keepw[lane + 32]) : 0;
        uint32_t inc1 = c1;
#pragma unroll
        for (int off = 1; off < 32; off <<= 1) {
            uint32_t v = __shfl_up_sync(0xFFFFFFFFu, inc1, off);
            if (lane >= off) inc1 += v;
        }
        if (lane + 32 < NWP) wpre[lane + 32] = tot0 + inc1 - c1;
    }
    __syncthreads();
    for (int r = tid; r < KTOP; r += 256) {
        int w = r >> 5;
        uint32_t word = keepw[w];
        uint32_t bit = 1u << (r & 31);
        if (word & bit) {
            uint32_t rank = wpre[w] + __popc(word & (bit - 1u));
            if (rank < MAXDET) {
                float4 bx = g_selbox[b * TPAD + r];
                float* o = ob + rank * 6;
                o[0] = bx.x; o[1] = bx.y; o[2] = bx.z; o[3] = bx.w;
                o[4] = g_selscore[b * TPAD + r];
                o[5] = g_selcls[b * TPAD + r];
            }
        }
    }
}

// ---------------- launch ----------------
extern "C" void kernel_launch(void* const* d_in, const int* in_sizes, int n_in,
                              void* d_out, int out_size) {
    const float* pred = (const float*)d_in[0];
    float* out = (float*)d_out;
    k_score<<<dim3((AA + 255) / 256, BB), 256>>>(pred);
    k_topk<<<BB, 1024>>>(pred);
    k_nms<<<dim3(10, BB), 256>>>(out);
}

// round 13
// speedup vs baseline: 1.2633x; 1.0405x over previous
#include <cuda_runtime.h>
#include <cstdint>

#define BB 32
#define AA 8400
#define NCH 84
#define NCC 80
#define KTOP 1500
#define TPAD 1536
#define SORTN 2048
#define MAXDET 300
#define NW 47
#define NWP 48
#define ITX 9                                   // ceil(8400/1024)
#define HDIM 4096                               // 20-bit key hist, range (0.25,1)
#define HBASE 0xBE800u                          // f2o(0.25f) >> 12

// ---------------- device scratch (static, allocation-free) ----------------
__device__ uint64_t g_keys[BB * AA];
__device__ uint32_t g_hist[BB * HDIM];          // zero-init; re-zeroed each run
__device__ float4   g_selbox[BB * TPAD];
__device__ float4   g_nmsbox[BB * TPAD];
__device__ float    g_selscore[BB * TPAD];
__device__ float    g_selcls[BB * TPAD];
__device__ uint8_t  g_clsSel[BB * TPAD];
__device__ uint32_t g_validbits[BB * NWP];
__device__ uint8_t  g_keepB[BB * TPAD];
__device__ uint32_t g_done[BB];

__device__ __forceinline__ uint32_t f2o(float f) {
    uint32_t u = __float_as_uint(f);
    return (u & 0x80000000u) ? ~u : (u | 0x80000000u);
}
__device__ __forceinline__ float o2f(uint32_t u) {
    return (u & 0x80000000u) ? __uint_as_float(u & 0x7FFFFFFFu)
                             : __uint_as_float(~u);
}
__device__ __forceinline__ uint64_t bshfl(uint64_t v, int i, int kk, int j) {
    uint64_t p = __shfl_xor_sync(0xFFFFFFFFu, v, j);
    bool up = (i & j) == 0;
    bool desc = (i & kk) == 0;
    bool takemax = (up == desc);
    return ((v > p) == takemax) ? v : p;
}
// 20-bit hist index for an orderable-hi; returns -1 if below range
__device__ __forceinline__ int histIdx(uint32_t hi) {
    uint32_t t = hi >> 12;
    if (t < HBASE) return -1;
    uint32_t idx = t - HBASE;
    return (idx > HDIM - 1) ? (HDIM - 1) : (int)idx;
}

// ---------------- stage 1: score max/argmax + free histogram ----------------
__global__ void __launch_bounds__(256) k_score(const float* __restrict__ pred) {
    const int Q = AA / 4;
    int t = blockIdx.x * blockDim.x + threadIdx.x;
    int b = blockIdx.y;
    int q = t >> 2;
    int h = t & 3;
    bool active = q < Q;
    if (q >= Q) q = Q - 1;

    const float4* p4 = (const float4*)pred;
    size_t base = ((size_t)b * NCH + 4) * Q + q;
    int c0 = h * 20;

    float4 best = p4[base + (size_t)c0 * Q];
    int cx = c0, cy = c0, cz = c0, cw = c0;
#pragma unroll
    for (int k = 1; k < 20; k++) {
        int c = c0 + k;
        float4 v = p4[base + (size_t)c * Q];
        if (v.x > best.x) { best.x = v.x; cx = c; }
        if (v.y > best.y) { best.y = v.y; cy = c; }
        if (v.z > best.z) { best.z = v.z; cz = c; }
        if (v.w > best.w) { best.w = v.w; cw = c; }
    }

    float sc[4] = {best.x, best.y, best.z, best.w};
    int   cl[4] = {cx, cy, cz, cw};
#pragma unroll
    for (int step = 1; step <= 2; step <<= 1) {
#pragma unroll
        for (int u = 0; u < 4; u++) {
            float so = __shfl_xor_sync(0xFFFFFFFFu, sc[u], step);
            int   co = __shfl_xor_sync(0xFFFFFFFFu, cl[u], step);
            if (so > sc[u] || (so == sc[u] && co < cl[u])) { sc[u] = so; cl[u] = co; }
        }
    }

    if (h == 0 && active) {
        int a0 = q * 4;
#pragma unroll
        for (int u = 0; u < 4; u++) {
            int a = a0 + u;
            float msc = (sc[u] > 0.25f) ? sc[u] : -1.0f;
            uint32_t hi = f2o(msc);
            uint32_t lo = ((uint32_t)(AA - 1 - a) << 7) | (uint32_t)cl[u];
            g_keys[b * AA + a] = ((uint64_t)hi << 32) | lo;
            int idx = histIdx(hi);
            if (idx >= 0) atomicAdd(&g_hist[b * HDIM + idx], 1u);
        }
    }
}

// ---------------- stage 2: hist-threshold select + hybrid bitonic ----------------
__global__ void __launch_bounds__(1024) k_topk(const float* __restrict__ pred) {
    __shared__ uint64_t sortbuf[SORTN];
    __shared__ uint32_t s_selCnt;
    __shared__ uint32_t warpSums[32], warpSufAfter[32];
    __shared__ int s_T;

    int b = blockIdx.x, tid = threadIdx.x;
    int warp = tid >> 5, lane = tid & 31;
    uint32_t lmlt = (1u << lane) - 1u;

    for (int i = tid; i < SORTN; i += 1024) sortbuf[i] = 0;
    for (int i = tid; i < TPAD; i += 1024) g_keepB[b * TPAD + i] = 0;
    if (tid == 0) { s_selCnt = 0; g_done[b] = 0; s_T = 0; }
    __syncthreads();

    // ---- find threshold bin T from the 4096-bin histogram ----
    const uint32_t* H = g_hist + b * HDIM;
    uint4 hb = ((const uint4*)H)[tid];          // bins [tid*4, tid*4+4)
    uint32_t mySum = hb.x + hb.y + hb.z + hb.w;

    uint32_t incl = mySum;
#pragma unroll
    for (int off = 1; off < 32; off <<= 1) {
        uint32_t v = __shfl_up_sync(0xFFFFFFFFu, incl, off);
        if (lane >= off) incl += v;
    }
    uint32_t warpsum = __shfl_sync(0xFFFFFFFFu, incl, 31);
    if (lane == 31) warpSums[warp] = warpsum;
    __syncthreads();
    if (warp == 0) {
        uint32_t ws = warpSums[lane];
        uint32_t wincl = ws;
#pragma unroll
        for (int off = 1; off < 32; off <<= 1) {
            uint32_t v = __shfl_up_sync(0xFFFFFFFFu, wincl, off);
            if (lane >= off) wincl += v;
        }
        uint32_t total = __shfl_sync(0xFFFFFFFFu, wincl, 31);
        warpSufAfter[lane] = total - wincl;
    }
    __syncthreads();

    uint32_t above = warpSufAfter[warp] + (warpsum - incl);
    if (above < KTOP && above + mySum >= KTOP && mySum > 0) {
        uint32_t bins[4] = {hb.x, hb.y, hb.z, hb.w};
        uint32_t cum = above;
#pragma unroll
        for (int k = 3; k >= 0; k--) {
            if (cum < KTOP && cum + bins[k] >= KTOP) s_T = tid * 4 + k;
            cum += bins[k];
        }
    }
    __syncthreads();
    int T = s_T;

    // ---- single sweep: select keys with histIdx >= T into sortbuf ----
    {
        uint64_t kv[ITX];
#pragma unroll
        for (int it = 0; it < ITX; it++) {
            int i = tid + (it << 10);
            kv[it] = (i < AA) ? g_keys[(size_t)b * AA + i] : 0ull;
        }
#pragma unroll
        for (int it = 0; it < ITX; it++) {
            int i = tid + (it << 10);
            bool toSel = false;
            if (i < AA) {
                int idx = histIdx((uint32_t)(kv[it] >> 32));
                toSel = (idx >= T);
            }
            uint32_t bal = __ballot_sync(0xFFFFFFFFu, toSel);
            uint32_t base = 0;
            if (bal) {
                uint32_t ldr = __ffs(bal) - 1;
                if (toSel && lane == (int)ldr)
                    base = atomicAdd(&s_selCnt, (uint32_t)__popc(bal));
                base = __shfl_sync(0xFFFFFFFFu, base, ldr);
                if (toSel) {
                    uint32_t pos = base + __popc(bal & lmlt);
                    if (pos < SORTN) sortbuf[pos] = kv[it];
                }
            }
        }
    }
    // re-zero this image's histogram for the next graph replay
    {
        uint4 z = make_uint4(0, 0, 0, 0);
        ((uint4*)(g_hist + b * HDIM))[tid] = z;
    }
    __syncthreads();

    // ---- hybrid bitonic sort descending, n=2048 (shfl j<32, smem j>=32) ----
    {
        int i0 = tid, i1 = tid + 1024;
        uint64_t v0 = sortbuf[i0], v1 = sortbuf[i1];
#pragma unroll
        for (int kk = 2; kk <= 32; kk <<= 1)
#pragma unroll
            for (int j = kk >> 1; j >= 1; j >>= 1) {
                v0 = bshfl(v0, i0, kk, j);
                v1 = bshfl(v1, i1, kk, j);
            }
        sortbuf[i0] = v0; sortbuf[i1] = v1;
        __syncthreads();
        for (int kk = 64; kk <= SORTN; kk <<= 1) {
            for (int j = kk >> 1; j >= 32; j >>= 1) {
                int p0 = ((tid & ~(j - 1)) << 1) | (tid & (j - 1));
                int p1 = p0 | j;
                uint64_t x = sortbuf[p0], y = sortbuf[p1];
                bool desc = (p0 & kk) == 0;
                if (desc ? (x < y) : (x > y)) { sortbuf[p0] = y; sortbuf[p1] = x; }
                __syncthreads();
            }
            v0 = sortbuf[i0]; v1 = sortbuf[i1];
#pragma unroll
            for (int j = 16; j >= 1; j >>= 1) {
                v0 = bshfl(v0, i0, kk, j);
                v1 = bshfl(v1, i1, kk, j);
            }
            sortbuf[i0] = v0; sortbuf[i1] = v1;
            __syncthreads();
        }
    }

    // ---- emit per-rank data + validity bitmap ----
    const float* pb = pred + (size_t)b * NCH * AA;
    const float SC1 = (float)(1.0 / 80.0 / 640.0);
    const float MULT = (float)(1.0 / 80.0);
#pragma unroll
    for (int rr = 0; rr < 2; rr++) {
        int r = tid + rr * 1024;
        bool inr = r < TPAD;
        bool validf = false;
        if (r < KTOP) {
            uint64_t k = sortbuf[r];
            uint32_t hi = (uint32_t)(k >> 32);
            uint32_t lo = (uint32_t)k;
            int cls = (int)(lo & 0x7Fu);
            uint32_t a = (uint32_t)(AA - 1) - (lo >> 7);
            float msc = o2f(hi);
            validf = msc > 0.25f;
            float bx0 = pb[(size_t)0 * AA + a];
            float bx1 = pb[(size_t)1 * AA + a];
            float bx2 = pb[(size_t)2 * AA + a];
            float bx3 = pb[(size_t)3 * AA + a];
            int o = b * TPAD + r;
            g_selbox[o] = make_float4(bx0, bx1, bx2, bx3);
            float off = (float)cls * MULT;
            g_nmsbox[o] = make_float4(bx0 * SC1 + off, bx1 * SC1 + off,
                                      bx2 * SC1 + off, bx3 * SC1 + off);
            g_selscore[o] = msc;
            g_selcls[o] = (float)cls;
            g_clsSel[o] = (uint8_t)cls;
        } else if (inr) {
            g_clsSel[b * TPAD + r] = 0xFFu;
        }
        uint32_t vb = __ballot_sync(0xFFFFFFFFu, validf);
        if (lane == 0 && inr) g_validbits[b * NWP + (r >> 5)] = vb;
    }
}

// ---------------- stage 3: per-(image,class) warp NMS + last-block output ----------------
__global__ void k_nms(float* __restrict__ out) {
    __shared__ uint8_t  sCls[TPAD];
    __shared__ uint32_t sValid[NWP];
    __shared__ uint16_t slist[8][TPAD];
    __shared__ uint32_t ssupp[8][NWP];
    __shared__ uint32_t keepw[NWP], wpre[NWP];
    __shared__ int s_last;
    int b = blockIdx.y;
    int tid = threadIdx.x, warp = tid >> 5, lane = tid & 31;
    int c = blockIdx.x * 8 + warp;              // 10 x 8 = 80 classes

    const uint32_t* gc4 = (const uint32_t*)(g_clsSel + b * TPAD);
    uint32_t* sc4 = (uint32_t*)sCls;
    for (int i = tid; i < TPAD / 4; i += 256) sc4[i] = gc4[i];
    if (tid < NWP) sValid[tid] = g_validbits[b * NWP + tid];
    __syncthreads();

    int cnt = 0;
    for (int w = 0; w < NW; w++) {
        int r = w * 32 + lane;
        bool m = (r < KTOP) && ((sValid[w] >> lane) & 1u) && (sCls[r] == (uint8_t)c);
        uint32_t bal = __ballot_sync(0xFFFFFFFFu, m);
        if (m) slist[warp][cnt + __popc(bal & ((1u << lane) - 1u))] = (uint16_t)r;
        cnt += __popc(bal);
    }
    int n = cnt;

    if (n > 0 && n <= 32) {
        float4 mb = make_float4(0.f, 0.f, 0.f, 0.f);
        int myr = -1;
        if (lane < n) { myr = slist[warp][lane]; mb = g_nmsbox[b * TPAD + myr]; }
        float areaM = (mb.z - mb.x) * (mb.w - mb.y);
        uint32_t supp = 0;
        for (int i = 0; i < n; i++) {
            if ((supp >> i) & 1u) continue;
            float ax = __shfl_sync(0xFFFFFFFFu, mb.x, i);
            float ay = __shfl_sync(0xFFFFFFFFu, mb.y, i);
            float az = __shfl_sync(0xFFFFFFFFu, mb.z, i);
            float aw = __shfl_sync(0xFFFFFFFFu, mb.w, i);
            float areaA = (az - ax) * (aw - ay);
            float lx = fmaxf(ax, mb.x), ly = fmaxf(ay, mb.y);
            float rx = fminf(az, mb.z), ry = fminf(aw, mb.w);
            float inter = fmaxf(rx - lx, 0.f) * fmaxf(ry - ly, 0.f);
            float iou = inter / (areaA + areaM - inter + 1e-7f);
            bool sbit = (lane > i) && (lane < n) && (iou > 0.45f);
            supp |= __ballot_sync(0xFFFFFFFFu, sbit);
        }
        if (lane < n && !((supp >> lane) & 1u)) g_keepB[b * TPAD + myr] = 1;
    } else if (n > 32) {
        int words = (n + 31) >> 5;
        for (int w = lane; w < words; w += 32) ssupp[warp][w] = 0;
        __syncwarp();
        for (int i = 0; i < n; i++) {
            if ((ssupp[warp][i >> 5] >> (i & 31)) & 1u) continue;
            float4 a = g_nmsbox[b * TPAD + slist[warp][i]];
            float areaA = (a.z - a.x) * (a.w - a.y);
            for (int w = i >> 5; w < words; w++) {
                int j = w * 32 + lane;
                bool sbit = false;
                if (j > i && j < n) {
                    float4 bb = g_nmsbox[b * TPAD + slist[warp][j]];
                    float areaB = (bb.z - bb.x) * (bb.w - bb.y);
                    float lx = fmaxf(a.x, bb.x), ly = fmaxf(a.y, bb.y);
                    float rx = fminf(a.z, bb.z), ry = fminf(a.w, bb.w);
                    float inter = fmaxf(rx - lx, 0.f) * fmaxf(ry - ly, 0.f);
                    float iou = inter / (areaA + areaB - inter + 1e-7f);
                    sbit = iou > 0.45f;
                }
                uint32_t bal = __ballot_sync(0xFFFFFFFFu, sbit);
                if (lane == 0 && bal) ssupp[warp][w] |= bal;
                __syncwarp();
            }
        }
        for (int j = lane; j < n; j += 32)
            if (!((ssupp[warp][j >> 5] >> (j & 31)) & 1u))
                g_keepB[b * TPAD + slist[warp][j]] = 1;
    }

    // ---- last block of this image performs compaction + output ----
    __threadfence();
    __syncthreads();
    if (tid == 0) s_last = (atomicAdd(&g_done[b], 1u) == gridDim.x - 1);
    __syncthreads();
    if (!s_last) return;

    float* ob = out + (size_t)b * (MAXDET * 6);
    for (int i = tid; i < MAXDET * 6; i += 256) ob[i] = 0.0f;

    uint8_t kb[6];
#pragma unroll
    for (int s = 0; s < 6; s++)
        kb[s] = g_keepB[b * TPAD + (warp * 6 + s) * 32 + lane];
#pragma unroll
    for (int s = 0; s < 6; s++) {
        uint32_t word = __ballot_sync(0xFFFFFFFFu, kb[s] != 0);
        if (lane == 0) keepw[warp * 6 + s] = word;
    }
    __syncthreads();
    if (warp == 0) {
        uint32_t c0 = (lane < NWP) ? __popc(keepw[lane]) : 0;
        uint32_t inc = c0;
#pragma unroll
        for (int off = 1; off < 32; off <<= 1) {
            uint32_t v = __shfl_up_sync(0xFFFFFFFFu, inc, off);
            if (lane >= off) inc += v;
        }
        if (lane < NWP) wpre[lane] = inc - c0;
        uint32_t tot0 = __shfl_sync(0xFFFFFFFFu, inc, 31);
        uint32_t c1 = (lane + 32 < NWP) ? __popc(keepw[lane + 32]) : 0;
        uint32_t inc1 = c1;
#pragma unroll
        for (int off = 1; off < 32; off <<= 1) {
            uint32_t v = __shfl_up_sync(0xFFFFFFFFu, inc1, off);
            if (lane >= off) inc1 += v;
        }
        if (lane + 32 < NWP) wpre[lane + 32] = tot0 + inc1 - c1;
    }
    __syncthreads();
    for (int r = tid; r < KTOP; r += 256) {
        int w = r >> 5;
        uint32_t word = keepw[w];
        uint32_t bit = 1u << (r & 31);
        if (word & bit) {
            uint32_t rank = wpre[w] + __popc(word & (bit - 1u));
            if (rank < MAXDET) {
                float4 bx = g_selbox[b * TPAD + r];
                float* o = ob + rank * 6;
                o[0] = bx.x; o[1] = bx.y; o[2] = bx.z; o[3] = bx.w;
                o[4] = g_selscore[b * TPAD + r];
                o[5] = g_selcls[b * TPAD + r];
            }
        }
    }
}

// ---------------- launch ----------------
extern "C" void kernel_launch(void* const* d_in, const int* in_sizes, int n_in,
                              void* d_out, int out_size) {
    const float* pred = (const float*)d_in[0];
    float* out = (float*)d_out;
    k_score<<<dim3((AA + 255) / 256, BB), 256>>>(pred);
    k_topk<<<BB, 1024>>>(pred);
    k_nms<<<dim3(10, BB), 256>>>(out);
}